// round 5
// baseline (speedup 1.0000x reference)
#include <cuda_runtime.h>
#include <math.h>

// Problem constants
#define M_TOT 32768            // 512*64 matrices
#define NMAT 32                // matrix side
#define BLOCKS 512
#define THREADS 256
#define WARPS_PER_BLOCK 8
#define NWARPS_TOTAL (BLOCKS * WARPS_PER_BLOCK)   // 4096 -> 8 matrices/warp
#define ROWSTRIDE 33           // padded row stride (bank-conflict free)
#define PART_ENTRIES (32 * ROWSTRIDE)             // 1056 (32 coords + sq per lane)

// Scratch (static device arrays; no runtime allocation allowed)
__device__ float g_L[(size_t)M_TOT * 1024];       // Cholesky factors, 134 MB
__device__ float g_part[BLOCKS * PART_ENTRIES];   // per-block partial sums
__device__ float g_sums[PART_ENTRIES];            // fully reduced sums
__device__ float g_stats[1025];                   // mean[32*32] (diag = logd mean) + factor

// ---------------------------------------------------------------------------
// Pass 1: warp-per-matrix Cholesky + Log-Cholesky statistic accumulation.
// Lane i owns row i of the matrix in registers. Right-looking Cholesky with
// shfl column broadcasts. Upper triangle self-zeroes (lik=0 for lane<k).
// ---------------------------------------------------------------------------
__global__ void __launch_bounds__(THREADS) chol_pass1(const float* __restrict__ X) {
    __shared__ float sred[WARPS_PER_BLOCK * PART_ENTRIES];  // 33.8 KB
    const int lane = threadIdx.x & 31;
    const int wl   = threadIdx.x >> 5;
    const int gw   = blockIdx.x * WARPS_PER_BLOCK + wl;

    float acc[32];
#pragma unroll
    for (int j = 0; j < 32; j++) acc[j] = 0.f;
    float accsq = 0.f;

    for (int m = gw; m < M_TOT; m += NWARPS_TOTAL) {
        // load row i (vectorized, 128B per lane)
        float a[32];
        const float4* src = reinterpret_cast<const float4*>(X + (size_t)m * 1024 + lane * 32);
#pragma unroll
        for (int q = 0; q < 8; q++) {
            float4 v = src[q];
            a[4*q+0] = v.x; a[4*q+1] = v.y; a[4*q+2] = v.z; a[4*q+3] = v.w;
        }

        float mydiag = 1.f;
#pragma unroll
        for (int k = 0; k < 32; k++) {
            float akk = __shfl_sync(0xffffffffu, a[k], k);
            float d   = sqrtf(akk);
            float lik = a[k] / d;            // lane==k: akk/d == d
            if (lane < k)  lik = 0.f;        // zero strictly-upper column entry
            if (lane == k) { lik = d; mydiag = d; }
            a[k] = lik;
            // rank-1 update of trailing submatrix (rows); column k broadcast via shfl
#pragma unroll
            for (int j = k + 1; j < 32; j++) {
                float ljk = __shfl_sync(0xffffffffu, lik, j);
                a[j] -= lik * ljk;
            }
        }
        float logd = logf(mydiag);

        // persist L row (upper already zero, diag = d)
        float4* dst = reinterpret_cast<float4*>(g_L + (size_t)m * 1024 + lane * 32);
#pragma unroll
        for (int q = 0; q < 8; q++) {
            float4 v;
            v.x = a[4*q+0]; v.y = a[4*q+1]; v.z = a[4*q+2]; v.w = a[4*q+3];
            dst[q] = v;
        }

        // accumulate Log-Cholesky coords: strict lower entries + logd in the diag slot
#pragma unroll
        for (int j = 0; j < 32; j++) {
            float v = (j < lane) ? a[j] : ((j == lane) ? logd : 0.f);
            acc[j] += v;
            accsq  += v * v;
        }
    }

    // per-warp accumulators -> shared, then block reduction -> g_part
#pragma unroll
    for (int j = 0; j < 32; j++)
        sred[wl * PART_ENTRIES + lane * ROWSTRIDE + j] = acc[j];
    sred[wl * PART_ENTRIES + lane * ROWSTRIDE + 32] = accsq;
    __syncthreads();

    for (int e = threadIdx.x; e < PART_ENTRIES; e += THREADS) {
        float s = 0.f;
#pragma unroll
        for (int w = 0; w < WARPS_PER_BLOCK; w++) s += sred[w * PART_ENTRIES + e];
        g_part[blockIdx.x * PART_ENTRIES + e] = s;
    }
}

// ---------------------------------------------------------------------------
// k2a: deterministic tree reduction of 512 block partials per entry.
// ---------------------------------------------------------------------------
__global__ void reduce2a() {
    __shared__ float red[BLOCKS];
    const int e = blockIdx.x;
    red[threadIdx.x] = g_part[threadIdx.x * PART_ENTRIES + e];
    __syncthreads();
#pragma unroll
    for (int s = BLOCKS / 2; s > 0; s >>= 1) {
        if ((int)threadIdx.x < s) red[threadIdx.x] += red[threadIdx.x + s];
        __syncthreads();
    }
    if (threadIdx.x == 0) g_sums[e] = red[0];
}

// ---------------------------------------------------------------------------
// k2b: means, variance = E||x||^2 - ||Ex||^2, factor = s / sqrt(var).
// ---------------------------------------------------------------------------
__global__ void stats_pass(const float* __restrict__ s_in) {
    __shared__ float red[1024];
    const int t = threadIdx.x;               // 1024 threads
    const int i = t >> 5, j = t & 31;
    const float invM = 1.0f / (float)M_TOT;

    float mean = g_sums[i * ROWSTRIDE + j] * invM;   // 0 for strictly-upper slots
    g_stats[i * 32 + j] = mean;
    float val = -mean * mean;
    if (t < 32) val += g_sums[t * ROWSTRIDE + 32] * invM;  // E||x||^2 contribution
    red[t] = val;
    __syncthreads();
#pragma unroll
    for (int s = 512; s > 0; s >>= 1) {
        if (t < s) red[t] += red[t + s];
        __syncthreads();
    }
    if (t == 0) {
        float var = red[0];
        g_stats[1024] = s_in[0] / sqrtf(var);
    }
}

// ---------------------------------------------------------------------------
// Pass 3: center + geodesic rescale, then X_out = L_out L_out^T.
// Warp-per-matrix; L_out tile in padded smem (broadcast reads), triangular
// dot products (k <= j; rows implicitly truncated since b[k]=0 for k>lane).
// ---------------------------------------------------------------------------
__global__ void __launch_bounds__(THREADS) out_pass(float* __restrict__ out) {
    __shared__ float smean[PART_ENTRIES];                   // padded mean (stride 33)
    __shared__ float tile[WARPS_PER_BLOCK * PART_ENTRIES];  // 33.8 KB
    __shared__ float sfac;

    for (int e = threadIdx.x; e < 1024; e += THREADS) {
        int mi = e >> 5, mj = e & 31;
        smean[mi * ROWSTRIDE + mj] = g_stats[e];
    }
    if (threadIdx.x == 0) sfac = g_stats[1024];
    __syncthreads();
    const float factor = sfac;

    const int lane = threadIdx.x & 31;
    const int wl   = threadIdx.x >> 5;
    const int gw   = blockIdx.x * WARPS_PER_BLOCK + wl;
    float* mytile  = tile + wl * PART_ENTRIES;

    for (int m = gw; m < M_TOT; m += NWARPS_TOTAL) {
        float a[32];
        const float4* src = reinterpret_cast<const float4*>(g_L + (size_t)m * 1024 + lane * 32);
#pragma unroll
        for (int q = 0; q < 8; q++) {
            float4 v = src[q];
            a[4*q+0] = v.x; a[4*q+1] = v.y; a[4*q+2] = v.z; a[4*q+3] = v.w;
        }
        // extract my diagonal element (compile-time-indexed selects)
        float d = 1.f;
#pragma unroll
        for (int j = 0; j < 32; j++) if (j == lane) d = a[j];

        const float logdc = logf(d) - smean[lane * ROWSTRIDE + lane];
        const float edc   = expf(factor * logdc);

        float b[32];
#pragma unroll
        for (int j = 0; j < 32; j++) {
            float v = (j < lane) ? factor * (a[j] - smean[lane * ROWSTRIDE + j]) : 0.f;
            if (j == lane) v = edc;
            b[j] = v;
        }

        // L_out tile to shared (conflict-free: bank = (lane + j) % 32)
#pragma unroll
        for (int j = 0; j < 32; j++) mytile[lane * ROWSTRIDE + j] = b[j];
        __syncwarp();

        // row i of X_out: o[j] = sum_{k<=j} b[k] * L_out[j][k] (b[k]=0 for k>i)
        float o[32];
#pragma unroll
        for (int j = 0; j < 32; j++) {
            float s = 0.f;
#pragma unroll
            for (int k = 0; k <= j; k++) s += b[k] * mytile[j * ROWSTRIDE + k];
            o[j] = s;
        }
        __syncwarp();   // tile reuse guard for next matrix

        float4* dst = reinterpret_cast<float4*>(out + (size_t)m * 1024 + lane * 32);
#pragma unroll
        for (int q = 0; q < 8; q++) {
            float4 v;
            v.x = o[4*q+0]; v.y = o[4*q+1]; v.z = o[4*q+2]; v.w = o[4*q+3];
            dst[q] = v;
        }
    }
}

extern "C" void kernel_launch(void* const* d_in, const int* in_sizes, int n_in,
                              void* d_out, int out_size) {
    const float* X = (const float*)d_in[0];
    const float* s = (const float*)d_in[1];
    float* out = (float*)d_out;

    chol_pass1<<<BLOCKS, THREADS>>>(X);
    reduce2a<<<PART_ENTRIES, BLOCKS>>>();
    stats_pass<<<1, 1024>>>(s);
    out_pass<<<BLOCKS, THREADS>>>(out);
}

// round 6
// speedup vs baseline: 1.0018x; 1.0018x over previous
#include <cuda_runtime.h>
#include <math.h>

// Problem constants
#define M_TOT 32768            // 512*64 matrices
#define NMAT 32                // matrix side
#define BLOCKS 512
#define THREADS 256
#define WARPS_PER_BLOCK 8
#define NWARPS_TOTAL (BLOCKS * WARPS_PER_BLOCK)   // 4096 -> 8 matrices/warp
#define ROWSTRIDE 33           // padded row stride (bank-conflict free)
#define PART_ENTRIES (32 * ROWSTRIDE)             // 1056 (32 coords + sq per lane)

// Scratch (static device arrays; no runtime allocation allowed)
__device__ float g_L[(size_t)M_TOT * 1024];       // Cholesky factors, 134 MB
__device__ float g_part[BLOCKS * PART_ENTRIES];   // per-block partial sums
__device__ float g_sums[PART_ENTRIES];            // fully reduced sums
__device__ float g_stats[1025];                   // mean[32*32] (diag = logd mean) + factor

// ---------------------------------------------------------------------------
// Pass 1: warp-per-matrix Cholesky + Log-Cholesky statistic accumulation.
// Lane i owns row i of the matrix in registers. Right-looking Cholesky with
// shfl column broadcasts. Upper triangle self-zeroes (lik=0 for lane<k).
// ---------------------------------------------------------------------------
__global__ void __launch_bounds__(THREADS) chol_pass1(const float* __restrict__ X) {
    __shared__ float sred[WARPS_PER_BLOCK * PART_ENTRIES];  // 33.8 KB
    const int lane = threadIdx.x & 31;
    const int wl   = threadIdx.x >> 5;
    const int gw   = blockIdx.x * WARPS_PER_BLOCK + wl;

    float acc[32];
#pragma unroll
    for (int j = 0; j < 32; j++) acc[j] = 0.f;
    float accsq = 0.f;

    for (int m = gw; m < M_TOT; m += NWARPS_TOTAL) {
        // load row i (vectorized, 128B per lane)
        float a[32];
        const float4* src = reinterpret_cast<const float4*>(X + (size_t)m * 1024 + lane * 32);
#pragma unroll
        for (int q = 0; q < 8; q++) {
            float4 v = src[q];
            a[4*q+0] = v.x; a[4*q+1] = v.y; a[4*q+2] = v.z; a[4*q+3] = v.w;
        }

        float mydiag = 1.f;
#pragma unroll
        for (int k = 0; k < 32; k++) {
            float akk = __shfl_sync(0xffffffffu, a[k], k);
            float d   = sqrtf(akk);
            float lik = a[k] / d;            // lane==k: akk/d == d
            if (lane < k)  lik = 0.f;        // zero strictly-upper column entry
            if (lane == k) { lik = d; mydiag = d; }
            a[k] = lik;
            // rank-1 update of trailing submatrix (rows); column k broadcast via shfl
#pragma unroll
            for (int j = k + 1; j < 32; j++) {
                float ljk = __shfl_sync(0xffffffffu, lik, j);
                a[j] -= lik * ljk;
            }
        }
        float logd = logf(mydiag);

        // persist L row (upper already zero, diag = d)
        float4* dst = reinterpret_cast<float4*>(g_L + (size_t)m * 1024 + lane * 32);
#pragma unroll
        for (int q = 0; q < 8; q++) {
            float4 v;
            v.x = a[4*q+0]; v.y = a[4*q+1]; v.z = a[4*q+2]; v.w = a[4*q+3];
            dst[q] = v;
        }

        // accumulate Log-Cholesky coords: strict lower entries + logd in the diag slot
#pragma unroll
        for (int j = 0; j < 32; j++) {
            float v = (j < lane) ? a[j] : ((j == lane) ? logd : 0.f);
            acc[j] += v;
            accsq  += v * v;
        }
    }

    // per-warp accumulators -> shared, then block reduction -> g_part
#pragma unroll
    for (int j = 0; j < 32; j++)
        sred[wl * PART_ENTRIES + lane * ROWSTRIDE + j] = acc[j];
    sred[wl * PART_ENTRIES + lane * ROWSTRIDE + 32] = accsq;
    __syncthreads();

    for (int e = threadIdx.x; e < PART_ENTRIES; e += THREADS) {
        float s = 0.f;
#pragma unroll
        for (int w = 0; w < WARPS_PER_BLOCK; w++) s += sred[w * PART_ENTRIES + e];
        g_part[blockIdx.x * PART_ENTRIES + e] = s;
    }
}

// ---------------------------------------------------------------------------
// k2a: deterministic tree reduction of 512 block partials per entry.
// ---------------------------------------------------------------------------
__global__ void reduce2a() {
    __shared__ float red[BLOCKS];
    const int e = blockIdx.x;
    red[threadIdx.x] = g_part[threadIdx.x * PART_ENTRIES + e];
    __syncthreads();
#pragma unroll
    for (int s = BLOCKS / 2; s > 0; s >>= 1) {
        if ((int)threadIdx.x < s) red[threadIdx.x] += red[threadIdx.x + s];
        __syncthreads();
    }
    if (threadIdx.x == 0) g_sums[e] = red[0];
}

// ---------------------------------------------------------------------------
// k2b: means, variance = E||x||^2 - ||Ex||^2, factor = s / sqrt(var).
// ---------------------------------------------------------------------------
__global__ void stats_pass(const float* __restrict__ s_in) {
    __shared__ float red[1024];
    const int t = threadIdx.x;               // 1024 threads
    const int i = t >> 5, j = t & 31;
    const float invM = 1.0f / (float)M_TOT;

    float mean = g_sums[i * ROWSTRIDE + j] * invM;   // 0 for strictly-upper slots
    g_stats[i * 32 + j] = mean;
    float val = -mean * mean;
    if (t < 32) val += g_sums[t * ROWSTRIDE + 32] * invM;  // E||x||^2 contribution
    red[t] = val;
    __syncthreads();
#pragma unroll
    for (int s = 512; s > 0; s >>= 1) {
        if (t < s) red[t] += red[t + s];
        __syncthreads();
    }
    if (t == 0) {
        float var = red[0];
        g_stats[1024] = s_in[0] / sqrtf(var);
    }
}

// ---------------------------------------------------------------------------
// Pass 3: center + geodesic rescale, then X_out = L_out L_out^T.
// Warp-per-matrix; L_out tile in padded smem (broadcast reads), triangular
// dot products (k <= j; rows implicitly truncated since b[k]=0 for k>lane).
// ---------------------------------------------------------------------------
__global__ void __launch_bounds__(THREADS) out_pass(float* __restrict__ out) {
    __shared__ float smean[PART_ENTRIES];                   // padded mean (stride 33)
    __shared__ float tile[WARPS_PER_BLOCK * PART_ENTRIES];  // 33.8 KB
    __shared__ float sfac;

    for (int e = threadIdx.x; e < 1024; e += THREADS) {
        int mi = e >> 5, mj = e & 31;
        smean[mi * ROWSTRIDE + mj] = g_stats[e];
    }
    if (threadIdx.x == 0) sfac = g_stats[1024];
    __syncthreads();
    const float factor = sfac;

    const int lane = threadIdx.x & 31;
    const int wl   = threadIdx.x >> 5;
    const int gw   = blockIdx.x * WARPS_PER_BLOCK + wl;
    float* mytile  = tile + wl * PART_ENTRIES;

    for (int m = gw; m < M_TOT; m += NWARPS_TOTAL) {
        float a[32];
        const float4* src = reinterpret_cast<const float4*>(g_L + (size_t)m * 1024 + lane * 32);
#pragma unroll
        for (int q = 0; q < 8; q++) {
            float4 v = src[q];
            a[4*q+0] = v.x; a[4*q+1] = v.y; a[4*q+2] = v.z; a[4*q+3] = v.w;
        }
        // extract my diagonal element (compile-time-indexed selects)
        float d = 1.f;
#pragma unroll
        for (int j = 0; j < 32; j++) if (j == lane) d = a[j];

        const float logdc = logf(d) - smean[lane * ROWSTRIDE + lane];
        const float edc   = expf(factor * logdc);

        float b[32];
#pragma unroll
        for (int j = 0; j < 32; j++) {
            float v = (j < lane) ? factor * (a[j] - smean[lane * ROWSTRIDE + j]) : 0.f;
            if (j == lane) v = edc;
            b[j] = v;
        }

        // L_out tile to shared (conflict-free: bank = (lane + j) % 32)
#pragma unroll
        for (int j = 0; j < 32; j++) mytile[lane * ROWSTRIDE + j] = b[j];
        __syncwarp();

        // row i of X_out: o[j] = sum_{k<=j} b[k] * L_out[j][k] (b[k]=0 for k>i)
        float o[32];
#pragma unroll
        for (int j = 0; j < 32; j++) {
            float s = 0.f;
#pragma unroll
            for (int k = 0; k <= j; k++) s += b[k] * mytile[j * ROWSTRIDE + k];
            o[j] = s;
        }
        __syncwarp();   // tile reuse guard for next matrix

        float4* dst = reinterpret_cast<float4*>(out + (size_t)m * 1024 + lane * 32);
#pragma unroll
        for (int q = 0; q < 8; q++) {
            float4 v;
            v.x = o[4*q+0]; v.y = o[4*q+1]; v.z = o[4*q+2]; v.w = o[4*q+3];
            dst[q] = v;
        }
    }
}

extern "C" void kernel_launch(void* const* d_in, const int* in_sizes, int n_in,
                              void* d_out, int out_size) {
    const float* X = (const float*)d_in[0];
    const float* s = (const float*)d_in[1];
    float* out = (float*)d_out;

    chol_pass1<<<BLOCKS, THREADS>>>(X);
    reduce2a<<<PART_ENTRIES, BLOCKS>>>();
    stats_pass<<<1, 1024>>>(s);
    out_pass<<<BLOCKS, THREADS>>>(out);
}

// round 7
// speedup vs baseline: 1.0022x; 1.0004x over previous
#include <cuda_runtime.h>
#include <math.h>

// Problem constants
#define M_TOT 32768            // 512*64 matrices
#define NMAT 32                // matrix side
#define BLOCKS 512
#define THREADS 256
#define WARPS_PER_BLOCK 8
#define NWARPS_TOTAL (BLOCKS * WARPS_PER_BLOCK)   // 4096 -> 8 matrices/warp
#define ROWSTRIDE 33           // padded row stride (bank-conflict free)
#define PART_ENTRIES (32 * ROWSTRIDE)             // 1056 (32 coords + sq per lane)

// Scratch (static device arrays; no runtime allocation allowed)
__device__ float g_L[(size_t)M_TOT * 1024];       // Cholesky factors, 134 MB
__device__ float g_part[BLOCKS * PART_ENTRIES];   // per-block partial sums
__device__ float g_sums[PART_ENTRIES];            // fully reduced sums
__device__ float g_stats[1025];                   // mean[32*32] (diag = logd mean) + factor

// ---------------------------------------------------------------------------
// Pass 1: warp-per-matrix Cholesky + Log-Cholesky statistic accumulation.
// Lane i owns row i of the matrix in registers. Right-looking Cholesky with
// shfl column broadcasts. Upper triangle self-zeroes (lik=0 for lane<k).
// ---------------------------------------------------------------------------
__global__ void __launch_bounds__(THREADS) chol_pass1(const float* __restrict__ X) {
    __shared__ float sred[WARPS_PER_BLOCK * PART_ENTRIES];  // 33.8 KB
    const int lane = threadIdx.x & 31;
    const int wl   = threadIdx.x >> 5;
    const int gw   = blockIdx.x * WARPS_PER_BLOCK + wl;

    float acc[32];
#pragma unroll
    for (int j = 0; j < 32; j++) acc[j] = 0.f;
    float accsq = 0.f;

    for (int m = gw; m < M_TOT; m += NWARPS_TOTAL) {
        // load row i (vectorized, 128B per lane)
        float a[32];
        const float4* src = reinterpret_cast<const float4*>(X + (size_t)m * 1024 + lane * 32);
#pragma unroll
        for (int q = 0; q < 8; q++) {
            float4 v = src[q];
            a[4*q+0] = v.x; a[4*q+1] = v.y; a[4*q+2] = v.z; a[4*q+3] = v.w;
        }

        float mydiag = 1.f;
#pragma unroll
        for (int k = 0; k < 32; k++) {
            float akk = __shfl_sync(0xffffffffu, a[k], k);
            float d   = sqrtf(akk);
            float lik = a[k] / d;            // lane==k: akk/d == d
            if (lane < k)  lik = 0.f;        // zero strictly-upper column entry
            if (lane == k) { lik = d; mydiag = d; }
            a[k] = lik;
            // rank-1 update of trailing submatrix (rows); column k broadcast via shfl
#pragma unroll
            for (int j = k + 1; j < 32; j++) {
                float ljk = __shfl_sync(0xffffffffu, lik, j);
                a[j] -= lik * ljk;
            }
        }
        float logd = logf(mydiag);

        // persist L row (upper already zero, diag = d)
        float4* dst = reinterpret_cast<float4*>(g_L + (size_t)m * 1024 + lane * 32);
#pragma unroll
        for (int q = 0; q < 8; q++) {
            float4 v;
            v.x = a[4*q+0]; v.y = a[4*q+1]; v.z = a[4*q+2]; v.w = a[4*q+3];
            dst[q] = v;
        }

        // accumulate Log-Cholesky coords: strict lower entries + logd in the diag slot
#pragma unroll
        for (int j = 0; j < 32; j++) {
            float v = (j < lane) ? a[j] : ((j == lane) ? logd : 0.f);
            acc[j] += v;
            accsq  += v * v;
        }
    }

    // per-warp accumulators -> shared, then block reduction -> g_part
#pragma unroll
    for (int j = 0; j < 32; j++)
        sred[wl * PART_ENTRIES + lane * ROWSTRIDE + j] = acc[j];
    sred[wl * PART_ENTRIES + lane * ROWSTRIDE + 32] = accsq;
    __syncthreads();

    for (int e = threadIdx.x; e < PART_ENTRIES; e += THREADS) {
        float s = 0.f;
#pragma unroll
        for (int w = 0; w < WARPS_PER_BLOCK; w++) s += sred[w * PART_ENTRIES + e];
        g_part[blockIdx.x * PART_ENTRIES + e] = s;
    }
}

// ---------------------------------------------------------------------------
// k2a: deterministic tree reduction of 512 block partials per entry.
// ---------------------------------------------------------------------------
__global__ void reduce2a() {
    __shared__ float red[BLOCKS];
    const int e = blockIdx.x;
    red[threadIdx.x] = g_part[threadIdx.x * PART_ENTRIES + e];
    __syncthreads();
#pragma unroll
    for (int s = BLOCKS / 2; s > 0; s >>= 1) {
        if ((int)threadIdx.x < s) red[threadIdx.x] += red[threadIdx.x + s];
        __syncthreads();
    }
    if (threadIdx.x == 0) g_sums[e] = red[0];
}

// ---------------------------------------------------------------------------
// k2b: means, variance = E||x||^2 - ||Ex||^2, factor = s / sqrt(var).
// ---------------------------------------------------------------------------
__global__ void stats_pass(const float* __restrict__ s_in) {
    __shared__ float red[1024];
    const int t = threadIdx.x;               // 1024 threads
    const int i = t >> 5, j = t & 31;
    const float invM = 1.0f / (float)M_TOT;

    float mean = g_sums[i * ROWSTRIDE + j] * invM;   // 0 for strictly-upper slots
    g_stats[i * 32 + j] = mean;
    float val = -mean * mean;
    if (t < 32) val += g_sums[t * ROWSTRIDE + 32] * invM;  // E||x||^2 contribution
    red[t] = val;
    __syncthreads();
#pragma unroll
    for (int s = 512; s > 0; s >>= 1) {
        if (t < s) red[t] += red[t + s];
        __syncthreads();
    }
    if (t == 0) {
        float var = red[0];
        g_stats[1024] = s_in[0] / sqrtf(var);
    }
}

// ---------------------------------------------------------------------------
// Pass 3: center + geodesic rescale, then X_out = L_out L_out^T.
// Warp-per-matrix; L_out tile in padded smem (broadcast reads), triangular
// dot products (k <= j; rows implicitly truncated since b[k]=0 for k>lane).
// ---------------------------------------------------------------------------
__global__ void __launch_bounds__(THREADS) out_pass(float* __restrict__ out) {
    __shared__ float smean[PART_ENTRIES];                   // padded mean (stride 33)
    __shared__ float tile[WARPS_PER_BLOCK * PART_ENTRIES];  // 33.8 KB
    __shared__ float sfac;

    for (int e = threadIdx.x; e < 1024; e += THREADS) {
        int mi = e >> 5, mj = e & 31;
        smean[mi * ROWSTRIDE + mj] = g_stats[e];
    }
    if (threadIdx.x == 0) sfac = g_stats[1024];
    __syncthreads();
    const float factor = sfac;

    const int lane = threadIdx.x & 31;
    const int wl   = threadIdx.x >> 5;
    const int gw   = blockIdx.x * WARPS_PER_BLOCK + wl;
    float* mytile  = tile + wl * PART_ENTRIES;

    for (int m = gw; m < M_TOT; m += NWARPS_TOTAL) {
        float a[32];
        const float4* src = reinterpret_cast<const float4*>(g_L + (size_t)m * 1024 + lane * 32);
#pragma unroll
        for (int q = 0; q < 8; q++) {
            float4 v = src[q];
            a[4*q+0] = v.x; a[4*q+1] = v.y; a[4*q+2] = v.z; a[4*q+3] = v.w;
        }
        // extract my diagonal element (compile-time-indexed selects)
        float d = 1.f;
#pragma unroll
        for (int j = 0; j < 32; j++) if (j == lane) d = a[j];

        const float logdc = logf(d) - smean[lane * ROWSTRIDE + lane];
        const float edc   = expf(factor * logdc);

        float b[32];
#pragma unroll
        for (int j = 0; j < 32; j++) {
            float v = (j < lane) ? factor * (a[j] - smean[lane * ROWSTRIDE + j]) : 0.f;
            if (j == lane) v = edc;
            b[j] = v;
        }

        // L_out tile to shared (conflict-free: bank = (lane + j) % 32)
#pragma unroll
        for (int j = 0; j < 32; j++) mytile[lane * ROWSTRIDE + j] = b[j];
        __syncwarp();

        // row i of X_out: o[j] = sum_{k<=j} b[k] * L_out[j][k] (b[k]=0 for k>i)
        float o[32];
#pragma unroll
        for (int j = 0; j < 32; j++) {
            float s = 0.f;
#pragma unroll
            for (int k = 0; k <= j; k++) s += b[k] * mytile[j * ROWSTRIDE + k];
            o[j] = s;
        }
        __syncwarp();   // tile reuse guard for next matrix

        float4* dst = reinterpret_cast<float4*>(out + (size_t)m * 1024 + lane * 32);
#pragma unroll
        for (int q = 0; q < 8; q++) {
            float4 v;
            v.x = o[4*q+0]; v.y = o[4*q+1]; v.z = o[4*q+2]; v.w = o[4*q+3];
            dst[q] = v;
        }
    }
}

extern "C" void kernel_launch(void* const* d_in, const int* in_sizes, int n_in,
                              void* d_out, int out_size) {
    const float* X = (const float*)d_in[0];
    const float* s = (const float*)d_in[1];
    float* out = (float*)d_out;

    chol_pass1<<<BLOCKS, THREADS>>>(X);
    reduce2a<<<PART_ENTRIES, BLOCKS>>>();
    stats_pass<<<1, 1024>>>(s);
    out_pass<<<BLOCKS, THREADS>>>(out);
}